// round 11
// baseline (speedup 1.0000x reference)
#include <cuda_runtime.h>
#include <math_constants.h>

#define B_      8
#define H_      32
#define DK_     128
#define DM_     4096
#define MAXLEN_ 4096
#define SPLIT_  4
#define KSPLIT_ 2
#define PFB_    32      // Wo-prefetch blocks appended to attn grid

// Scratch (no allocation allowed in kernel_launch)
__device__ float g_qp[KSPLIT_][B_ * DM_];   // q projection partials
__device__ float g_kp[KSPLIT_][B_ * DM_];
__device__ float g_vp[KSPLIT_][B_ * DM_];
__device__ float g_op[KSPLIT_][B_ * DM_];   // output projection partials
__device__ float g_attn[B_ * DM_];
__device__ float g_pm[B_ * H_ * SPLIT_];
__device__ float g_pl[B_ * H_ * SPLIT_];
__device__ float g_pa[B_ * H_ * SPLIT_ * DK_];

__device__ __forceinline__ float dot4(float4 a, float4 b) {
    return a.x * b.x + a.y * b.y + a.z * b.z + a.w * b.w;
}
__device__ __forceinline__ float4 add4(float4 a, float4 b) {
    return make_float4(a.x + b.x, a.y + b.y, a.z + b.z, a.w + b.w);
}

// ---------------------------------------------------------------------------
// Split-K GEMV partial (R8 config — best measured: DRAM 47%, 18.3us proj_out).
// 8 warps x 4 rows = 32 rows/block; slice = DM/KSPLIT = 2048 cols.
// x slice staged in smem (64KB); W streamed with __ldcs + L2 prefetch of the
// chunk-after-next. Epilogue: butterfly transpose-reduce.
// ---------------------------------------------------------------------------
#define SLICE4_ (DM_ / KSPLIT_ / 4)          // float4 cols per slice (512)
#define NIT_    (DM_ / KSPLIT_ / 256)        // column chunks per slice (8)

__device__ __forceinline__ void proj_body(const float4* __restrict__ x4,
                                          const float* __restrict__ W,
                                          float* __restrict__ yp,
                                          int kslice, float4* xs4) {
    const int tid  = threadIdx.x;
    const int warp = tid >> 5;
    const int lane = tid & 31;
    const int row0 = blockIdx.x * 32 + warp * 4;
    const int cbase = kslice * SLICE4_;      // float4 column base in x

    // stage x slice into smem
    #pragma unroll
    for (int i = tid; i < B_ * SLICE4_; i += 256) {
        const int b = i >> 9;                // /512
        const int c = i & (SLICE4_ - 1);
        xs4[i] = __ldg(x4 + b * (DM_ / 4) + cbase + c);
    }

    // warm L2 with the first two chunks of this warp's W rows while staging
    {
        const float* pf0 = W + (size_t)(row0 + (lane >> 3)) * DM_
                         + (size_t)cbase * 4 + (lane & 7) * 32;
        asm volatile("prefetch.global.L2 [%0];" :: "l"(pf0));
        asm volatile("prefetch.global.L2 [%0];" :: "l"(pf0 + 256));
    }
    __syncthreads();

    float acc[32];                            // acc[r*8+b]
    #pragma unroll
    for (int i = 0; i < 32; i++) acc[i] = 0.f;

    const float4* w0p = (const float4*)(W + (size_t)(row0 + 0) * DM_) + cbase;
    const float4* w1p = (const float4*)(W + (size_t)(row0 + 1) * DM_) + cbase;
    const float4* w2p = (const float4*)(W + (size_t)(row0 + 2) * DM_) + cbase;
    const float4* w3p = (const float4*)(W + (size_t)(row0 + 3) * DM_) + cbase;
    const float*  pfb = W + (size_t)(row0 + (lane >> 3)) * DM_
                      + (size_t)cbase * 4 + (lane & 7) * 32;

    #pragma unroll 2
    for (int it = 0; it < NIT_; ++it) {
        if (it + 2 < NIT_) {
            asm volatile("prefetch.global.L2 [%0];" :: "l"(pfb + (it + 2) * 256));
        }

        const int c0 = it * 64 + lane;        // local float4 col
        const int c1 = c0 + 32;
        const float4 wa0 = __ldcs(w0p + c0), wb0 = __ldcs(w0p + c1);
        const float4 wa1 = __ldcs(w1p + c0), wb1 = __ldcs(w1p + c1);
        const float4 wa2 = __ldcs(w2p + c0), wb2 = __ldcs(w2p + c1);
        const float4 wa3 = __ldcs(w3p + c0), wb3 = __ldcs(w3p + c1);
        #pragma unroll
        for (int b = 0; b < B_; b++) {
            const float4 xa = xs4[b * SLICE4_ + c0];
            acc[0 * 8 + b] += dot4(wa0, xa);
            acc[1 * 8 + b] += dot4(wa1, xa);
            acc[2 * 8 + b] += dot4(wa2, xa);
            acc[3 * 8 + b] += dot4(wa3, xa);
            const float4 xb = xs4[b * SLICE4_ + c1];
            acc[0 * 8 + b] += dot4(wb0, xb);
            acc[1 * 8 + b] += dot4(wb1, xb);
            acc[2 * 8 + b] += dot4(wb2, xb);
            acc[3 * 8 + b] += dot4(wb3, xb);
        }
    }

    // Butterfly transpose-reduce: lane L ends holding full sum of acc[L].
    #pragma unroll
    for (int o = 16; o >= 1; o >>= 1) {
        const bool up = (lane & o) != 0;
        #pragma unroll
        for (int k = 0; k < o; k++) {
            const float keep = up ? acc[k + o] : acc[k];
            const float send = up ? acc[k]     : acc[k + o];
            acc[k] = keep + __shfl_xor_sync(0xffffffffu, send, o);
        }
    }
    const int r = lane >> 3;
    const int b = lane & 7;
    yp[b * DM_ + row0 + r] = acc[0];
}

__global__ void __launch_bounds__(256, 2)
proj_qkv_kernel(const float* __restrict__ q_in, const float* __restrict__ k_in,
                const float* __restrict__ v_in,
                const float* __restrict__ Wq, const float* __restrict__ Wk,
                const float* __restrict__ Wv) {
    extern __shared__ float4 xs4[];
    const int ks = blockIdx.y;
    const float* x; const float* W; float* y;
    if (blockIdx.z == 0)      { x = q_in; W = Wq; y = g_qp[ks]; }
    else if (blockIdx.z == 1) { x = k_in; W = Wk; y = g_kp[ks]; }
    else                      { x = v_in; W = Wv; y = g_vp[ks]; }
    proj_body((const float4*)x, W, y, ks, xs4);
}

__global__ void __launch_bounds__(256, 2)
proj_out_kernel(const float* __restrict__ Wo) {
    extern __shared__ float4 xs4[];
    proj_body((const float4*)g_attn, Wo, g_op[blockIdx.y], blockIdx.y, xs4);
}

__global__ void __launch_bounds__(256)
final_add_kernel(const float* __restrict__ bo, float* __restrict__ out) {
    const int i = blockIdx.x * 256 + threadIdx.x;   // i in [0, B_*DM_)
    out[i] = g_op[0][i] + g_op[1][i] + bo[i & (DM_ - 1)];
}

// ---------------------------------------------------------------------------
// Attention, split-K over keys (at HBM roofline) + Wo L2-prefetch role blocks.
// Blocks with blockIdx.x >= B_*H_ prefetch a 2MB slice of Wo into L2 and exit,
// so Wo is L2-resident when proj_out launches. Attention's K/V stream uses
// __ldcs (evict-first) so the prefetched lines survive.
// ---------------------------------------------------------------------------
__global__ void __launch_bounds__(256)
attn_kernel(const float* __restrict__ kc, const float* __restrict__ vc,
            const float* __restrict__ bq, const float* __restrict__ bk,
            const float* __restrict__ bv, const int* __restrict__ cache_len_p,
            const float* __restrict__ Wo) {
    const int bh = blockIdx.x;

    if (bh >= B_ * H_) {                      // Wo prefetch role
        if (blockIdx.y == 0) {
            const int pb  = bh - B_ * H_;     // 0..PFB_-1
            const int tid = threadIdx.x;
            // 64MB total: PFB_ blocks x 256 thr x 64 lines x 128B
            const float* base = Wo + ((size_t)pb * 16384 + tid) * 32;
            #pragma unroll 8
            for (int k = 0; k < 64; k++) {
                asm volatile("prefetch.global.L2 [%0];"
                             :: "l"(base + (size_t)k * 256 * 32));
            }
        }
        return;
    }

    const int b  = bh >> 5;
    const int h  = bh & 31;
    const int s  = blockIdx.y;
    const int L  = cache_len_p[0] + 1;
    const int Lm1 = L - 1;
    const int chunk = (L + SPLIT_ - 1) / SPLIT_;
    const int start = s * chunk;
    const int end   = min(start + chunk, L);

    const int tid  = threadIdx.x;
    const int warp = tid >> 5;
    const int lane = tid & 31;

    const int voff = b * DM_ + h * DK_;
    const float scale = 0.08838834764831843f; // 1/sqrt(128)

    float4 q4   = ((const float4*)(bq + h * DK_))[lane];
    float4 Knew = ((const float4*)(bk + h * DK_))[lane];
    float4 Vnew = ((const float4*)(bv + h * DK_))[lane];
    #pragma unroll
    for (int ks = 0; ks < KSPLIT_; ks++) {
        q4   = add4(q4,   ((const float4*)(g_qp[ks] + voff))[lane]);
        Knew = add4(Knew, ((const float4*)(g_kp[ks] + voff))[lane]);
        Vnew = add4(Vnew, ((const float4*)(g_vp[ks] + voff))[lane]);
    }
    q4.x *= scale; q4.y *= scale; q4.z *= scale; q4.w *= scale;

    const float4* kb = (const float4*)(kc + (((size_t)b * H_ + h) * (size_t)MAXLEN_) * DK_);
    const float4* vb = (const float4*)(vc + (((size_t)b * H_ + h) * (size_t)MAXLEN_) * DK_);

    float m = -CUDART_INF_F;
    float lsum = 0.f;
    float4 a = make_float4(0.f, 0.f, 0.f, 0.f);

    int key = start + warp;
    for (; key + 24 < end; key += 32) {
        const int k1 = key, k2 = key + 8, k3 = key + 16, k4 = key + 24;
        float4 K1 = __ldcs(kb + (size_t)k1 * 32 + lane);
        float4 K2 = __ldcs(kb + (size_t)k2 * 32 + lane);
        float4 K3 = __ldcs(kb + (size_t)k3 * 32 + lane);
        float4 K4 = __ldcs(kb + (size_t)k4 * 32 + lane);
        float4 V1 = __ldcs(vb + (size_t)k1 * 32 + lane);
        float4 V2 = __ldcs(vb + (size_t)k2 * 32 + lane);
        float4 V3 = __ldcs(vb + (size_t)k3 * 32 + lane);
        float4 V4 = __ldcs(vb + (size_t)k4 * 32 + lane);
        if (k1 == Lm1) { K1 = Knew; V1 = Vnew; }
        if (k2 == Lm1) { K2 = Knew; V2 = Vnew; }
        if (k3 == Lm1) { K3 = Knew; V3 = Vnew; }
        if (k4 == Lm1) { K4 = Knew; V4 = Vnew; }

        float s1 = dot4(q4, K1);
        float s2 = dot4(q4, K2);
        float s3 = dot4(q4, K3);
        float s4 = dot4(q4, K4);
        #pragma unroll
        for (int o = 16; o > 0; o >>= 1) {
            s1 += __shfl_xor_sync(0xffffffffu, s1, o);
            s2 += __shfl_xor_sync(0xffffffffu, s2, o);
            s3 += __shfl_xor_sync(0xffffffffu, s3, o);
            s4 += __shfl_xor_sync(0xffffffffu, s4, o);
        }

        const float mn = fmaxf(fmaxf(m, fmaxf(s1, s2)), fmaxf(s3, s4));
        const float corr = __expf(m - mn);
        const float p1 = __expf(s1 - mn);
        const float p2 = __expf(s2 - mn);
        const float p3 = __expf(s3 - mn);
        const float p4 = __expf(s4 - mn);
        lsum = lsum * corr + (p1 + p2) + (p3 + p4);
        a.x = a.x * corr + p1 * V1.x + p2 * V2.x + p3 * V3.x + p4 * V4.x;
        a.y = a.y * corr + p1 * V1.y + p2 * V2.y + p3 * V3.y + p4 * V4.y;
        a.z = a.z * corr + p1 * V1.z + p2 * V2.z + p3 * V3.z + p4 * V4.z;
        a.w = a.w * corr + p1 * V1.w + p2 * V2.w + p3 * V3.w + p4 * V4.w;
        m = mn;
    }
    for (; key < end; key += 8) {
        float4 K1 = __ldcs(kb + (size_t)key * 32 + lane);
        float4 V1 = __ldcs(vb + (size_t)key * 32 + lane);
        if (key == Lm1) { K1 = Knew; V1 = Vnew; }
        float s1 = dot4(q4, K1);
        #pragma unroll
        for (int o = 16; o > 0; o >>= 1) s1 += __shfl_xor_sync(0xffffffffu, s1, o);
        const float mn = fmaxf(m, s1);
        const float corr = __expf(m - mn);
        const float p1 = __expf(s1 - mn);
        lsum = lsum * corr + p1;
        a.x = a.x * corr + p1 * V1.x;
        a.y = a.y * corr + p1 * V1.y;
        a.z = a.z * corr + p1 * V1.z;
        a.w = a.w * corr + p1 * V1.w;
        m = mn;
    }

    // cross-warp combine -> unnormalized block partial
    __shared__ float  sm_m[8];
    __shared__ float  sm_l[8];
    __shared__ float4 sm_a[8][32];
    if (lane == 0) { sm_m[warp] = m; sm_l[warp] = lsum; }
    sm_a[warp][lane] = a;
    __syncthreads();

    if (tid < 128) {
        float M = sm_m[0];
        #pragma unroll
        for (int w = 1; w < 8; w++) M = fmaxf(M, sm_m[w]);
        float Ls = 0.f, o = 0.f;
        const float* sa = (const float*)sm_a;  // [8][128]
        #pragma unroll
        for (int w = 0; w < 8; w++) {
            const float e = __expf(sm_m[w] - M);
            Ls += e * sm_l[w];
            o  += e * sa[w * 128 + tid];
        }
        const int idx = bh * SPLIT_ + s;
        g_pa[idx * DK_ + tid] = o;
        if (tid == 0) { g_pm[idx] = M; g_pl[idx] = Ls; }
    }
}

__global__ void __launch_bounds__(128)
attn_reduce_kernel() {
    const int bh = blockIdx.x;
    const int d  = threadIdx.x;
    float M = -CUDART_INF_F;
    #pragma unroll
    for (int s = 0; s < SPLIT_; s++) M = fmaxf(M, g_pm[bh * SPLIT_ + s]);
    float Ls = 0.f, o = 0.f;
    #pragma unroll
    for (int s = 0; s < SPLIT_; s++) {
        const int idx = bh * SPLIT_ + s;
        const float e = __expf(g_pm[idx] - M);
        Ls += e * g_pl[idx];
        o  += e * g_pa[idx * DK_ + d];
    }
    g_attn[bh * DK_ + d] = o / Ls;
}

// ---------------------------------------------------------------------------
extern "C" void kernel_launch(void* const* d_in, const int* in_sizes, int n_in,
                              void* d_out, int out_size) {
    const float* query = (const float*)d_in[0];
    const float* keyv  = (const float*)d_in[1];
    const float* value = (const float*)d_in[2];
    const float* kc    = (const float*)d_in[3];
    const float* vc    = (const float*)d_in[4];
    const float* Wq    = (const float*)d_in[5];
    const float* bq    = (const float*)d_in[6];
    const float* Wk    = (const float*)d_in[7];
    const float* bk    = (const float*)d_in[8];
    const float* Wv    = (const float*)d_in[9];
    const float* bv    = (const float*)d_in[10];
    const float* Wo    = (const float*)d_in[11];
    const float* bo    = (const float*)d_in[12];
    const int*   clp   = (const int*)d_in[13];

    const int smem = B_ * SLICE4_ * sizeof(float4);   // 64 KB
    cudaFuncSetAttribute(proj_qkv_kernel, cudaFuncAttributeMaxDynamicSharedMemorySize, smem);
    cudaFuncSetAttribute(proj_out_kernel, cudaFuncAttributeMaxDynamicSharedMemorySize, smem);

    dim3 gqkv(DM_ / 32, KSPLIT_, 3);
    proj_qkv_kernel<<<gqkv, 256, smem>>>(query, keyv, value, Wq, Wk, Wv);
    dim3 gattn(B_ * H_ + PFB_, SPLIT_);
    attn_kernel<<<gattn, 256>>>(kc, vc, bq, bk, bv, clp, Wo);
    attn_reduce_kernel<<<B_ * H_, 128>>>();
    dim3 gout(DM_ / 32, KSPLIT_);
    proj_out_kernel<<<gout, 256, smem>>>(Wo);
    final_add_kernel<<<B_ * DM_ / 256, 256>>>(bo, (float*)d_out);
}

// round 12
// speedup vs baseline: 1.0327x; 1.0327x over previous
#include <cuda_runtime.h>
#include <math_constants.h>

#define B_      8
#define H_      32
#define DK_     128
#define DM_     4096
#define MAXLEN_ 4096
#define SPLIT_  4
#define KSPLIT_ 2

// Scratch (no allocation allowed in kernel_launch)
__device__ float g_qp[KSPLIT_][B_ * DM_];   // q projection partials
__device__ float g_kp[KSPLIT_][B_ * DM_];
__device__ float g_vp[KSPLIT_][B_ * DM_];
__device__ float g_op[KSPLIT_][B_ * DM_];   // output projection partials
__device__ float g_pm[B_ * H_ * SPLIT_];    // attn partial max   [bh][s]
__device__ float g_pl[B_ * H_ * SPLIT_];    // attn partial sum   [bh][s]
__device__ float g_pa[B_ * H_ * SPLIT_ * DK_]; // attn partial acc [bh][s][d]

__device__ __forceinline__ float dot4(float4 a, float4 b) {
    return a.x * b.x + a.y * b.y + a.z * b.z + a.w * b.w;
}
__device__ __forceinline__ float4 add4(float4 a, float4 b) {
    return make_float4(a.x + b.x, a.y + b.y, a.z + b.z, a.w + b.w);
}

// ---------------------------------------------------------------------------
// Split-K GEMV partial (R8 config — best measured). 8 warps x 4 rows = 32
// rows/block; slice = DM/KSPLIT = 2048 cols. x slice staged in smem (64KB);
// W streamed with __ldcs + L2 prefetch of the chunk-after-next.
// FOLD_REDUCE: proj_out variant stages x by combining the attention split-K
// partials (g_pm/g_pl/g_pa, all L2-hot) inline — the separate attn_reduce
// kernel and g_attn round-trip are deleted.
// Epilogue: butterfly transpose-reduce -> 31 shuffles, 1 STG per lane.
// ---------------------------------------------------------------------------
#define SLICE4_ (DM_ / KSPLIT_ / 4)          // float4 cols per slice (512)
#define NIT_    (DM_ / KSPLIT_ / 256)        // column chunks per slice (8)

template <bool FOLD_REDUCE>
__device__ __forceinline__ void proj_body(const float4* __restrict__ x4,
                                          const float* __restrict__ W,
                                          float* __restrict__ yp,
                                          int kslice, float4* xs4) {
    const int tid  = threadIdx.x;
    const int warp = tid >> 5;
    const int lane = tid & 31;
    const int row0 = blockIdx.x * 32 + warp * 4;
    const int cbase = kslice * SLICE4_;      // float4 column base in x

    // stage x slice into smem
    if (!FOLD_REDUCE) {
        #pragma unroll
        for (int i = tid; i < B_ * SLICE4_; i += 256) {
            const int b = i >> 9;            // /512
            const int c = i & (SLICE4_ - 1);
            xs4[i] = __ldg(x4 + b * (DM_ / 4) + cbase + c);
        }
    } else {
        // x[b][j] = attention output = sum_s e_s * pa_s[d] / sum_s e_s * pl_s
        for (int i = tid; i < B_ * SLICE4_; i += 256) {
            const int b  = i >> 9;
            const int c  = i & (SLICE4_ - 1);
            const int j4 = cbase + c;        // global float4 col (0..1023)
            const int h  = j4 >> 5;          // head
            const int d4 = j4 & 31;          // float4 index within head
            const int bh = b * H_ + h;
            const float4 pm = *(const float4*)(g_pm + bh * SPLIT_);
            const float4 pl = *(const float4*)(g_pl + bh * SPLIT_);
            const float M  = fmaxf(fmaxf(pm.x, pm.y), fmaxf(pm.z, pm.w));
            const float e0 = __expf(pm.x - M);
            const float e1 = __expf(pm.y - M);
            const float e2 = __expf(pm.z - M);
            const float e3 = __expf(pm.w - M);
            const float Ls = e0 * pl.x + e1 * pl.y + e2 * pl.z + e3 * pl.w;
            const float4 a0 = ((const float4*)(g_pa + (bh * SPLIT_ + 0) * DK_))[d4];
            const float4 a1 = ((const float4*)(g_pa + (bh * SPLIT_ + 1) * DK_))[d4];
            const float4 a2 = ((const float4*)(g_pa + (bh * SPLIT_ + 2) * DK_))[d4];
            const float4 a3 = ((const float4*)(g_pa + (bh * SPLIT_ + 3) * DK_))[d4];
            const float inv = 1.0f / Ls;
            float4 o;
            o.x = (e0 * a0.x + e1 * a1.x + e2 * a2.x + e3 * a3.x) * inv;
            o.y = (e0 * a0.y + e1 * a1.y + e2 * a2.y + e3 * a3.y) * inv;
            o.z = (e0 * a0.z + e1 * a1.z + e2 * a2.z + e3 * a3.z) * inv;
            o.w = (e0 * a0.w + e1 * a1.w + e2 * a2.w + e3 * a3.w) * inv;
            xs4[i] = o;
        }
    }

    // warm L2 with the first two chunks of this warp's W rows while staging
    {
        const float* pf0 = W + (size_t)(row0 + (lane >> 3)) * DM_
                         + (size_t)cbase * 4 + (lane & 7) * 32;
        asm volatile("prefetch.global.L2 [%0];" :: "l"(pf0));
        asm volatile("prefetch.global.L2 [%0];" :: "l"(pf0 + 256));
    }
    __syncthreads();

    float acc[32];                            // acc[r*8+b]
    #pragma unroll
    for (int i = 0; i < 32; i++) acc[i] = 0.f;

    const float4* w0p = (const float4*)(W + (size_t)(row0 + 0) * DM_) + cbase;
    const float4* w1p = (const float4*)(W + (size_t)(row0 + 1) * DM_) + cbase;
    const float4* w2p = (const float4*)(W + (size_t)(row0 + 2) * DM_) + cbase;
    const float4* w3p = (const float4*)(W + (size_t)(row0 + 3) * DM_) + cbase;
    const float*  pfb = W + (size_t)(row0 + (lane >> 3)) * DM_
                      + (size_t)cbase * 4 + (lane & 7) * 32;

    #pragma unroll 2
    for (int it = 0; it < NIT_; ++it) {
        if (it + 2 < NIT_) {
            asm volatile("prefetch.global.L2 [%0];" :: "l"(pfb + (it + 2) * 256));
        }

        const int c0 = it * 64 + lane;        // local float4 col
        const int c1 = c0 + 32;
        const float4 wa0 = __ldcs(w0p + c0), wb0 = __ldcs(w0p + c1);
        const float4 wa1 = __ldcs(w1p + c0), wb1 = __ldcs(w1p + c1);
        const float4 wa2 = __ldcs(w2p + c0), wb2 = __ldcs(w2p + c1);
        const float4 wa3 = __ldcs(w3p + c0), wb3 = __ldcs(w3p + c1);
        #pragma unroll
        for (int b = 0; b < B_; b++) {
            const float4 xa = xs4[b * SLICE4_ + c0];
            acc[0 * 8 + b] += dot4(wa0, xa);
            acc[1 * 8 + b] += dot4(wa1, xa);
            acc[2 * 8 + b] += dot4(wa2, xa);
            acc[3 * 8 + b] += dot4(wa3, xa);
            const float4 xb = xs4[b * SLICE4_ + c1];
            acc[0 * 8 + b] += dot4(wb0, xb);
            acc[1 * 8 + b] += dot4(wb1, xb);
            acc[2 * 8 + b] += dot4(wb2, xb);
            acc[3 * 8 + b] += dot4(wb3, xb);
        }
    }

    // Butterfly transpose-reduce: lane L ends holding full sum of acc[L].
    #pragma unroll
    for (int o = 16; o >= 1; o >>= 1) {
        const bool up = (lane & o) != 0;
        #pragma unroll
        for (int k = 0; k < o; k++) {
            const float keep = up ? acc[k + o] : acc[k];
            const float send = up ? acc[k]     : acc[k + o];
            acc[k] = keep + __shfl_xor_sync(0xffffffffu, send, o);
        }
    }
    const int r = lane >> 3;
    const int b = lane & 7;
    yp[b * DM_ + row0 + r] = acc[0];
}

__global__ void __launch_bounds__(256, 2)
proj_qkv_kernel(const float* __restrict__ q_in, const float* __restrict__ k_in,
                const float* __restrict__ v_in,
                const float* __restrict__ Wq, const float* __restrict__ Wk,
                const float* __restrict__ Wv) {
    extern __shared__ float4 xs4[];
    const int ks = blockIdx.y;
    const float* x; const float* W; float* y;
    if (blockIdx.z == 0)      { x = q_in; W = Wq; y = g_qp[ks]; }
    else if (blockIdx.z == 1) { x = k_in; W = Wk; y = g_kp[ks]; }
    else                      { x = v_in; W = Wv; y = g_vp[ks]; }
    proj_body<false>((const float4*)x, W, y, ks, xs4);
}

__global__ void __launch_bounds__(256, 2)
proj_out_kernel(const float* __restrict__ Wo) {
    extern __shared__ float4 xs4[];
    proj_body<true>(nullptr, Wo, g_op[blockIdx.y], blockIdx.y, xs4);
}

__global__ void __launch_bounds__(256)
final_add_kernel(const float* __restrict__ bo, float* __restrict__ out) {
    const int i = blockIdx.x * 256 + threadIdx.x;   // i in [0, B_*DM_)
    out[i] = g_op[0][i] + g_op[1][i] + bo[i & (DM_ - 1)];
}

// ---------------------------------------------------------------------------
// Attention, split-K over keys (at HBM roofline — R8 version, prefetch role
// reverted). Writes unnormalized split partials; proj_out folds the combine.
// ---------------------------------------------------------------------------
__global__ void __launch_bounds__(256)
attn_kernel(const float* __restrict__ kc, const float* __restrict__ vc,
            const float* __restrict__ bq, const float* __restrict__ bk,
            const float* __restrict__ bv, const int* __restrict__ cache_len_p) {
    const int bh = blockIdx.x;
    const int b  = bh >> 5;
    const int h  = bh & 31;
    const int s  = blockIdx.y;
    const int L  = cache_len_p[0] + 1;
    const int Lm1 = L - 1;
    const int chunk = (L + SPLIT_ - 1) / SPLIT_;
    const int start = s * chunk;
    const int end   = min(start + chunk, L);

    const int tid  = threadIdx.x;
    const int warp = tid >> 5;
    const int lane = tid & 31;

    const int voff = b * DM_ + h * DK_;
    const float scale = 0.08838834764831843f; // 1/sqrt(128)

    float4 q4   = ((const float4*)(bq + h * DK_))[lane];
    float4 Knew = ((const float4*)(bk + h * DK_))[lane];
    float4 Vnew = ((const float4*)(bv + h * DK_))[lane];
    #pragma unroll
    for (int ks = 0; ks < KSPLIT_; ks++) {
        q4   = add4(q4,   ((const float4*)(g_qp[ks] + voff))[lane]);
        Knew = add4(Knew, ((const float4*)(g_kp[ks] + voff))[lane]);
        Vnew = add4(Vnew, ((const float4*)(g_vp[ks] + voff))[lane]);
    }
    q4.x *= scale; q4.y *= scale; q4.z *= scale; q4.w *= scale;

    const float4* kb = (const float4*)(kc + (((size_t)b * H_ + h) * (size_t)MAXLEN_) * DK_);
    const float4* vb = (const float4*)(vc + (((size_t)b * H_ + h) * (size_t)MAXLEN_) * DK_);

    float m = -CUDART_INF_F;
    float lsum = 0.f;
    float4 a = make_float4(0.f, 0.f, 0.f, 0.f);

    int key = start + warp;
    for (; key + 24 < end; key += 32) {
        const int k1 = key, k2 = key + 8, k3 = key + 16, k4 = key + 24;
        float4 K1 = __ldcs(kb + (size_t)k1 * 32 + lane);
        float4 K2 = __ldcs(kb + (size_t)k2 * 32 + lane);
        float4 K3 = __ldcs(kb + (size_t)k3 * 32 + lane);
        float4 K4 = __ldcs(kb + (size_t)k4 * 32 + lane);
        float4 V1 = __ldcs(vb + (size_t)k1 * 32 + lane);
        float4 V2 = __ldcs(vb + (size_t)k2 * 32 + lane);
        float4 V3 = __ldcs(vb + (size_t)k3 * 32 + lane);
        float4 V4 = __ldcs(vb + (size_t)k4 * 32 + lane);
        if (k1 == Lm1) { K1 = Knew; V1 = Vnew; }
        if (k2 == Lm1) { K2 = Knew; V2 = Vnew; }
        if (k3 == Lm1) { K3 = Knew; V3 = Vnew; }
        if (k4 == Lm1) { K4 = Knew; V4 = Vnew; }

        float s1 = dot4(q4, K1);
        float s2 = dot4(q4, K2);
        float s3 = dot4(q4, K3);
        float s4 = dot4(q4, K4);
        #pragma unroll
        for (int o = 16; o > 0; o >>= 1) {
            s1 += __shfl_xor_sync(0xffffffffu, s1, o);
            s2 += __shfl_xor_sync(0xffffffffu, s2, o);
            s3 += __shfl_xor_sync(0xffffffffu, s3, o);
            s4 += __shfl_xor_sync(0xffffffffu, s4, o);
        }

        const float mn = fmaxf(fmaxf(m, fmaxf(s1, s2)), fmaxf(s3, s4));
        const float corr = __expf(m - mn);
        const float p1 = __expf(s1 - mn);
        const float p2 = __expf(s2 - mn);
        const float p3 = __expf(s3 - mn);
        const float p4 = __expf(s4 - mn);
        lsum = lsum * corr + (p1 + p2) + (p3 + p4);
        a.x = a.x * corr + p1 * V1.x + p2 * V2.x + p3 * V3.x + p4 * V4.x;
        a.y = a.y * corr + p1 * V1.y + p2 * V2.y + p3 * V3.y + p4 * V4.y;
        a.z = a.z * corr + p1 * V1.z + p2 * V2.z + p3 * V3.z + p4 * V4.z;
        a.w = a.w * corr + p1 * V1.w + p2 * V2.w + p3 * V3.w + p4 * V4.w;
        m = mn;
    }
    for (; key < end; key += 8) {
        float4 K1 = __ldcs(kb + (size_t)key * 32 + lane);
        float4 V1 = __ldcs(vb + (size_t)key * 32 + lane);
        if (key == Lm1) { K1 = Knew; V1 = Vnew; }
        float s1 = dot4(q4, K1);
        #pragma unroll
        for (int o = 16; o > 0; o >>= 1) s1 += __shfl_xor_sync(0xffffffffu, s1, o);
        const float mn = fmaxf(m, s1);
        const float corr = __expf(m - mn);
        const float p1 = __expf(s1 - mn);
        lsum = lsum * corr + p1;
        a.x = a.x * corr + p1 * V1.x;
        a.y = a.y * corr + p1 * V1.y;
        a.z = a.z * corr + p1 * V1.z;
        a.w = a.w * corr + p1 * V1.w;
        m = mn;
    }

    // cross-warp combine -> unnormalized block partial
    __shared__ float  sm_m[8];
    __shared__ float  sm_l[8];
    __shared__ float4 sm_a[8][32];
    if (lane == 0) { sm_m[warp] = m; sm_l[warp] = lsum; }
    sm_a[warp][lane] = a;
    __syncthreads();

    if (tid < 128) {
        float M = sm_m[0];
        #pragma unroll
        for (int w = 1; w < 8; w++) M = fmaxf(M, sm_m[w]);
        float Ls = 0.f, o = 0.f;
        const float* sa = (const float*)sm_a;  // [8][128]
        #pragma unroll
        for (int w = 0; w < 8; w++) {
            const float e = __expf(sm_m[w] - M);
            Ls += e * sm_l[w];
            o  += e * sa[w * 128 + tid];
        }
        const int idx = bh * SPLIT_ + s;
        g_pa[idx * DK_ + tid] = o;
        if (tid == 0) { g_pm[idx] = M; g_pl[idx] = Ls; }
    }
}

// ---------------------------------------------------------------------------
extern "C" void kernel_launch(void* const* d_in, const int* in_sizes, int n_in,
                              void* d_out, int out_size) {
    const float* query = (const float*)d_in[0];
    const float* keyv  = (const float*)d_in[1];
    const float* value = (const float*)d_in[2];
    const float* kc    = (const float*)d_in[3];
    const float* vc    = (const float*)d_in[4];
    const float* Wq    = (const float*)d_in[5];
    const float* bq    = (const float*)d_in[6];
    const float* Wk    = (const float*)d_in[7];
    const float* bk    = (const float*)d_in[8];
    const float* Wv    = (const float*)d_in[9];
    const float* bv    = (const float*)d_in[10];
    const float* Wo    = (const float*)d_in[11];
    const float* bo    = (const float*)d_in[12];
    const int*   clp   = (const int*)d_in[13];

    const int smem = B_ * SLICE4_ * sizeof(float4);   // 64 KB
    cudaFuncSetAttribute(proj_qkv_kernel, cudaFuncAttributeMaxDynamicSharedMemorySize, smem);
    cudaFuncSetAttribute(proj_out_kernel, cudaFuncAttributeMaxDynamicSharedMemorySize, smem);

    dim3 gqkv(DM_ / 32, KSPLIT_, 3);
    proj_qkv_kernel<<<gqkv, 256, smem>>>(query, keyv, value, Wq, Wk, Wv);
    dim3 gattn(B_ * H_, SPLIT_);
    attn_kernel<<<gattn, 256>>>(kc, vc, bq, bk, bv, clp);
    dim3 gout(DM_ / 32, KSPLIT_);
    proj_out_kernel<<<gout, 256, smem>>>(Wo);
    final_add_kernel<<<B_ * DM_ / 256, 256>>>(bo, (float*)d_out);
}

// round 13
// speedup vs baseline: 1.0546x; 1.0212x over previous
#include <cuda_runtime.h>
#include <math_constants.h>

#define B_      8
#define H_      32
#define DK_     128
#define DM_     4096
#define MAXLEN_ 4096
#define SPLIT_  4
#define KSPLIT_ 2

// Scratch (no allocation allowed in kernel_launch)
__device__ float g_qp[KSPLIT_][B_ * DM_];   // q projection partials
__device__ float g_kp[KSPLIT_][B_ * DM_];
__device__ float g_vp[KSPLIT_][B_ * DM_];
__device__ float g_op0[B_ * DM_];           // proj_out slice-0 partial
__device__ float g_attn[B_ * DM_];
__device__ float g_pm[B_ * H_ * SPLIT_];
__device__ float g_pl[B_ * H_ * SPLIT_];
__device__ float g_pa[B_ * H_ * SPLIT_ * DK_];
__device__ int   g_flag[DM_ / 32];          // per row-block: slice-0 done

__device__ __forceinline__ float dot4(float4 a, float4 b) {
    return a.x * b.x + a.y * b.y + a.z * b.z + a.w * b.w;
}
__device__ __forceinline__ float4 add4(float4 a, float4 b) {
    return make_float4(a.x + b.x, a.y + b.y, a.z + b.z, a.w + b.w);
}

// ---------------------------------------------------------------------------
// Split-K GEMV core (R8 config — best measured). 8 warps x 4 rows = 32
// rows/block; slice = DM/KSPLIT = 2048 cols. x slice staged in smem (64KB);
// W streamed with __ldcs + L2 prefetch of the chunk-after-next.
// Returns lane L's reduced output value (output index row0 + (L>>3), batch
// L&7) after a butterfly transpose-reduce.
// ---------------------------------------------------------------------------
#define SLICE4_ (DM_ / KSPLIT_ / 4)          // float4 cols per slice (512)
#define NIT_    (DM_ / KSPLIT_ / 256)        // column chunks per slice (8)

__device__ __forceinline__ float proj_core(const float4* __restrict__ x4,
                                           const float* __restrict__ W,
                                           int kslice, float4* xs4,
                                           int* out_row0) {
    const int tid  = threadIdx.x;
    const int warp = tid >> 5;
    const int lane = tid & 31;
    const int row0 = blockIdx.x * 32 + warp * 4;
    const int cbase = kslice * SLICE4_;      // float4 column base in x
    *out_row0 = row0;

    // stage x slice into smem
    #pragma unroll
    for (int i = tid; i < B_ * SLICE4_; i += 256) {
        const int b = i >> 9;                // /512
        const int c = i & (SLICE4_ - 1);
        xs4[i] = __ldg(x4 + b * (DM_ / 4) + cbase + c);
    }

    // warm L2 with the first two chunks of this warp's W rows while staging
    {
        const float* pf0 = W + (size_t)(row0 + (lane >> 3)) * DM_
                         + (size_t)cbase * 4 + (lane & 7) * 32;
        asm volatile("prefetch.global.L2 [%0];" :: "l"(pf0));
        asm volatile("prefetch.global.L2 [%0];" :: "l"(pf0 + 256));
    }
    __syncthreads();

    float acc[32];                            // acc[r*8+b]
    #pragma unroll
    for (int i = 0; i < 32; i++) acc[i] = 0.f;

    const float4* w0p = (const float4*)(W + (size_t)(row0 + 0) * DM_) + cbase;
    const float4* w1p = (const float4*)(W + (size_t)(row0 + 1) * DM_) + cbase;
    const float4* w2p = (const float4*)(W + (size_t)(row0 + 2) * DM_) + cbase;
    const float4* w3p = (const float4*)(W + (size_t)(row0 + 3) * DM_) + cbase;
    const float*  pfb = W + (size_t)(row0 + (lane >> 3)) * DM_
                      + (size_t)cbase * 4 + (lane & 7) * 32;

    #pragma unroll 2
    for (int it = 0; it < NIT_; ++it) {
        if (it + 2 < NIT_) {
            asm volatile("prefetch.global.L2 [%0];" :: "l"(pfb + (it + 2) * 256));
        }

        const int c0 = it * 64 + lane;        // local float4 col
        const int c1 = c0 + 32;
        const float4 wa0 = __ldcs(w0p + c0), wb0 = __ldcs(w0p + c1);
        const float4 wa1 = __ldcs(w1p + c0), wb1 = __ldcs(w1p + c1);
        const float4 wa2 = __ldcs(w2p + c0), wb2 = __ldcs(w2p + c1);
        const float4 wa3 = __ldcs(w3p + c0), wb3 = __ldcs(w3p + c1);
        #pragma unroll
        for (int b = 0; b < B_; b++) {
            const float4 xa = xs4[b * SLICE4_ + c0];
            acc[0 * 8 + b] += dot4(wa0, xa);
            acc[1 * 8 + b] += dot4(wa1, xa);
            acc[2 * 8 + b] += dot4(wa2, xa);
            acc[3 * 8 + b] += dot4(wa3, xa);
            const float4 xb = xs4[b * SLICE4_ + c1];
            acc[0 * 8 + b] += dot4(wb0, xb);
            acc[1 * 8 + b] += dot4(wb1, xb);
            acc[2 * 8 + b] += dot4(wb2, xb);
            acc[3 * 8 + b] += dot4(wb3, xb);
        }
    }

    // Butterfly transpose-reduce: lane L ends holding full sum of acc[L].
    #pragma unroll
    for (int o = 16; o >= 1; o >>= 1) {
        const bool up = (lane & o) != 0;
        #pragma unroll
        for (int k = 0; k < o; k++) {
            const float keep = up ? acc[k + o] : acc[k];
            const float send = up ? acc[k]     : acc[k + o];
            acc[k] = keep + __shfl_xor_sync(0xffffffffu, send, o);
        }
    }
    return acc[0];
}

__global__ void __launch_bounds__(256, 2)
proj_qkv_kernel(const float* __restrict__ q_in, const float* __restrict__ k_in,
                const float* __restrict__ v_in,
                const float* __restrict__ Wq, const float* __restrict__ Wk,
                const float* __restrict__ Wv) {
    extern __shared__ float4 xs4[];
    // clear proj_out combine flags (stream-ordered before proj_out; replay-safe)
    if (blockIdx.x == 0 && blockIdx.y == 0 && blockIdx.z == 0 &&
        threadIdx.x < DM_ / 32) {
        g_flag[threadIdx.x] = 0;
    }
    const int ks = blockIdx.y;
    const float* x; const float* W; float* y;
    if (blockIdx.z == 0)      { x = q_in; W = Wq; y = g_qp[ks]; }
    else if (blockIdx.z == 1) { x = k_in; W = Wk; y = g_kp[ks]; }
    else                      { x = v_in; W = Wv; y = g_vp[ks]; }
    int row0;
    const float v = proj_core((const float4*)x, W, ks, xs4, &row0);
    const int lane = threadIdx.x & 31;
    y[(lane & 7) * DM_ + row0 + (lane >> 3)] = v;
}

// proj_out with in-kernel deterministic combine:
//   slice 0 (blockIdx.y==0): write partial to g_op0, fence, set flag.
//   slice 1 (blockIdx.y==1): compute own partial, wait for flag, combine with
//   slice-0 partial + bias, write final output. All 256 blocks are
//   co-resident (256 <= 148 SMs x 2 CTAs), so the wait cannot deadlock.
__global__ void __launch_bounds__(256, 2)
proj_out_kernel(const float* __restrict__ Wo, const float* __restrict__ bo,
                float* __restrict__ out) {
    extern __shared__ float4 xs4[];
    const int ks = blockIdx.y;
    int row0;
    const float v = proj_core((const float4*)g_attn, Wo, ks, xs4, &row0);
    const int lane = threadIdx.x & 31;
    const int b    = lane & 7;
    const int col  = row0 + (lane >> 3);
    const int idx  = b * DM_ + col;

    if (ks == 0) {
        g_op0[idx] = v;
        __threadfence();
        __syncthreads();
        if (threadIdx.x == 0) atomicExch(&g_flag[blockIdx.x], 1);
    } else {
        if (threadIdx.x == 0) {
            while (atomicAdd(&g_flag[blockIdx.x], 0) == 0) __nanosleep(64);
        }
        __syncthreads();
        __threadfence();
        const float p0 = __ldcg(&g_op0[idx]);
        out[idx] = (p0 + v) + __ldg(&bo[col]);
    }
}

// ---------------------------------------------------------------------------
// Attention, split-K over keys (at HBM roofline — R8 version, unchanged).
// ---------------------------------------------------------------------------
__global__ void __launch_bounds__(256)
attn_kernel(const float* __restrict__ kc, const float* __restrict__ vc,
            const float* __restrict__ bq, const float* __restrict__ bk,
            const float* __restrict__ bv, const int* __restrict__ cache_len_p) {
    const int bh = blockIdx.x;
    const int b  = bh >> 5;
    const int h  = bh & 31;
    const int s  = blockIdx.y;
    const int L  = cache_len_p[0] + 1;
    const int Lm1 = L - 1;
    const int chunk = (L + SPLIT_ - 1) / SPLIT_;
    const int start = s * chunk;
    const int end   = min(start + chunk, L);

    const int tid  = threadIdx.x;
    const int warp = tid >> 5;
    const int lane = tid & 31;

    const int voff = b * DM_ + h * DK_;
    const float scale = 0.08838834764831843f; // 1/sqrt(128)

    float4 q4   = ((const float4*)(bq + h * DK_))[lane];
    float4 Knew = ((const float4*)(bk + h * DK_))[lane];
    float4 Vnew = ((const float4*)(bv + h * DK_))[lane];
    #pragma unroll
    for (int ks = 0; ks < KSPLIT_; ks++) {
        q4   = add4(q4,   ((const float4*)(g_qp[ks] + voff))[lane]);
        Knew = add4(Knew, ((const float4*)(g_kp[ks] + voff))[lane]);
        Vnew = add4(Vnew, ((const float4*)(g_vp[ks] + voff))[lane]);
    }
    q4.x *= scale; q4.y *= scale; q4.z *= scale; q4.w *= scale;

    const float4* kb = (const float4*)(kc + (((size_t)b * H_ + h) * (size_t)MAXLEN_) * DK_);
    const float4* vb = (const float4*)(vc + (((size_t)b * H_ + h) * (size_t)MAXLEN_) * DK_);

    float m = -CUDART_INF_F;
    float lsum = 0.f;
    float4 a = make_float4(0.f, 0.f, 0.f, 0.f);

    int key = start + warp;
    for (; key + 24 < end; key += 32) {
        const int k1 = key, k2 = key + 8, k3 = key + 16, k4 = key + 24;
        float4 K1 = __ldcs(kb + (size_t)k1 * 32 + lane);
        float4 K2 = __ldcs(kb + (size_t)k2 * 32 + lane);
        float4 K3 = __ldcs(kb + (size_t)k3 * 32 + lane);
        float4 K4 = __ldcs(kb + (size_t)k4 * 32 + lane);
        float4 V1 = __ldcs(vb + (size_t)k1 * 32 + lane);
        float4 V2 = __ldcs(vb + (size_t)k2 * 32 + lane);
        float4 V3 = __ldcs(vb + (size_t)k3 * 32 + lane);
        float4 V4 = __ldcs(vb + (size_t)k4 * 32 + lane);
        if (k1 == Lm1) { K1 = Knew; V1 = Vnew; }
        if (k2 == Lm1) { K2 = Knew; V2 = Vnew; }
        if (k3 == Lm1) { K3 = Knew; V3 = Vnew; }
        if (k4 == Lm1) { K4 = Knew; V4 = Vnew; }

        float s1 = dot4(q4, K1);
        float s2 = dot4(q4, K2);
        float s3 = dot4(q4, K3);
        float s4 = dot4(q4, K4);
        #pragma unroll
        for (int o = 16; o > 0; o >>= 1) {
            s1 += __shfl_xor_sync(0xffffffffu, s1, o);
            s2 += __shfl_xor_sync(0xffffffffu, s2, o);
            s3 += __shfl_xor_sync(0xffffffffu, s3, o);
            s4 += __shfl_xor_sync(0xffffffffu, s4, o);
        }

        const float mn = fmaxf(fmaxf(m, fmaxf(s1, s2)), fmaxf(s3, s4));
        const float corr = __expf(m - mn);
        const float p1 = __expf(s1 - mn);
        const float p2 = __expf(s2 - mn);
        const float p3 = __expf(s3 - mn);
        const float p4 = __expf(s4 - mn);
        lsum = lsum * corr + (p1 + p2) + (p3 + p4);
        a.x = a.x * corr + p1 * V1.x + p2 * V2.x + p3 * V3.x + p4 * V4.x;
        a.y = a.y * corr + p1 * V1.y + p2 * V2.y + p3 * V3.y + p4 * V4.y;
        a.z = a.z * corr + p1 * V1.z + p2 * V2.z + p3 * V3.z + p4 * V4.z;
        a.w = a.w * corr + p1 * V1.w + p2 * V2.w + p3 * V3.w + p4 * V4.w;
        m = mn;
    }
    for (; key < end; key += 8) {
        float4 K1 = __ldcs(kb + (size_t)key * 32 + lane);
        float4 V1 = __ldcs(vb + (size_t)key * 32 + lane);
        if (key == Lm1) { K1 = Knew; V1 = Vnew; }
        float s1 = dot4(q4, K1);
        #pragma unroll
        for (int o = 16; o > 0; o >>= 1) s1 += __shfl_xor_sync(0xffffffffu, s1, o);
        const float mn = fmaxf(m, s1);
        const float corr = __expf(m - mn);
        const float p1 = __expf(s1 - mn);
        lsum = lsum * corr + p1;
        a.x = a.x * corr + p1 * V1.x;
        a.y = a.y * corr + p1 * V1.y;
        a.z = a.z * corr + p1 * V1.z;
        a.w = a.w * corr + p1 * V1.w;
        m = mn;
    }

    // cross-warp combine -> unnormalized block partial
    __shared__ float  sm_m[8];
    __shared__ float  sm_l[8];
    __shared__ float4 sm_a[8][32];
    if (lane == 0) { sm_m[warp] = m; sm_l[warp] = lsum; }
    sm_a[warp][lane] = a;
    __syncthreads();

    if (tid < 128) {
        float M = sm_m[0];
        #pragma unroll
        for (int w = 1; w < 8; w++) M = fmaxf(M, sm_m[w]);
        float Ls = 0.f, o = 0.f;
        const float* sa = (const float*)sm_a;  // [8][128]
        #pragma unroll
        for (int w = 0; w < 8; w++) {
            const float e = __expf(sm_m[w] - M);
            Ls += e * sm_l[w];
            o  += e * sa[w * 128 + tid];
        }
        const int idx = bh * SPLIT_ + s;
        g_pa[idx * DK_ + tid] = o;
        if (tid == 0) { g_pm[idx] = M; g_pl[idx] = Ls; }
    }
}

__global__ void __launch_bounds__(128)
attn_reduce_kernel() {
    const int bh = blockIdx.x;
    const int d  = threadIdx.x;
    float M = -CUDART_INF_F;
    #pragma unroll
    for (int s = 0; s < SPLIT_; s++) M = fmaxf(M, g_pm[bh * SPLIT_ + s]);
    float Ls = 0.f, o = 0.f;
    #pragma unroll
    for (int s = 0; s < SPLIT_; s++) {
        const int idx = bh * SPLIT_ + s;
        const float e = __expf(g_pm[idx] - M);
        Ls += e * g_pl[idx];
        o  += e * g_pa[idx * DK_ + d];
    }
    g_attn[bh * DK_ + d] = o / Ls;
}

// ---------------------------------------------------------------------------
extern "C" void kernel_launch(void* const* d_in, const int* in_sizes, int n_in,
                              void* d_out, int out_size) {
    const float* query = (const float*)d_in[0];
    const float* keyv  = (const float*)d_in[1];
    const float* value = (const float*)d_in[2];
    const float* kc    = (const float*)d_in[3];
    const float* vc    = (const float*)d_in[4];
    const float* Wq    = (const float*)d_in[5];
    const float* bq    = (const float*)d_in[6];
    const float* Wk    = (const float*)d_in[7];
    const float* bk    = (const float*)d_in[8];
    const float* Wv    = (const float*)d_in[9];
    const float* bv    = (const float*)d_in[10];
    const float* Wo    = (const float*)d_in[11];
    const float* bo    = (const float*)d_in[12];
    const int*   clp   = (const int*)d_in[13];

    const int smem = B_ * SLICE4_ * sizeof(float4);   // 64 KB
    cudaFuncSetAttribute(proj_qkv_kernel, cudaFuncAttributeMaxDynamicSharedMemorySize, smem);
    cudaFuncSetAttribute(proj_out_kernel, cudaFuncAttributeMaxDynamicSharedMemorySize, smem);

    dim3 gqkv(DM_ / 32, KSPLIT_, 3);
    proj_qkv_kernel<<<gqkv, 256, smem>>>(query, keyv, value, Wq, Wk, Wv);
    dim3 gattn(B_ * H_, SPLIT_);
    attn_kernel<<<gattn, 256>>>(kc, vc, bq, bk, bv, clp);
    attn_reduce_kernel<<<B_ * H_, 128>>>();
    dim3 gout(DM_ / 32, KSPLIT_);
    proj_out_kernel<<<gout, 256, smem>>>(Wo, bo, (float*)d_out);
}

// round 14
// speedup vs baseline: 1.0549x; 1.0003x over previous
#include <cuda_runtime.h>
#include <math_constants.h>

#define B_      8
#define H_      32
#define DK_     128
#define DM_     4096
#define MAXLEN_ 4096
#define SPLIT_  4
#define KSPLIT_ 2

// Scratch (no allocation allowed in kernel_launch)
__device__ float g_qp[KSPLIT_][B_ * DM_];   // q projection partials
__device__ float g_kp[KSPLIT_][B_ * DM_];
__device__ float g_vp[KSPLIT_][B_ * DM_];
__device__ float g_op0[B_ * DM_];           // proj_out slice-0 partial
__device__ float g_attn[B_ * DM_];
__device__ float g_pm[B_ * H_ * SPLIT_];
__device__ float g_pl[B_ * H_ * SPLIT_];
__device__ float g_pa[B_ * H_ * SPLIT_ * DK_];
__device__ int   g_flag[DM_ / 32];          // proj_out: slice-0 done flags
__device__ int   g_cnt[B_ * H_];            // attn: split-arrival counters

__device__ __forceinline__ float dot4(float4 a, float4 b) {
    return a.x * b.x + a.y * b.y + a.z * b.z + a.w * b.w;
}
__device__ __forceinline__ float4 add4(float4 a, float4 b) {
    return make_float4(a.x + b.x, a.y + b.y, a.z + b.z, a.w + b.w);
}

// ---------------------------------------------------------------------------
// Split-K GEMV core (R8 config — best measured). 8 warps x 4 rows = 32
// rows/block; slice = DM/KSPLIT = 2048 cols. x slice staged in smem (64KB);
// W streamed with __ldcs + L2 prefetch of the chunk-after-next.
// Returns lane L's reduced output (row row0+(L>>3), batch L&7).
// ---------------------------------------------------------------------------
#define SLICE4_ (DM_ / KSPLIT_ / 4)          // float4 cols per slice (512)
#define NIT_    (DM_ / KSPLIT_ / 256)        // column chunks per slice (8)

__device__ __forceinline__ float proj_core(const float4* __restrict__ x4,
                                           const float* __restrict__ W,
                                           int kslice, float4* xs4,
                                           int* out_row0) {
    const int tid  = threadIdx.x;
    const int warp = tid >> 5;
    const int lane = tid & 31;
    const int row0 = blockIdx.x * 32 + warp * 4;
    const int cbase = kslice * SLICE4_;      // float4 column base in x
    *out_row0 = row0;

    // stage x slice into smem
    #pragma unroll
    for (int i = tid; i < B_ * SLICE4_; i += 256) {
        const int b = i >> 9;                // /512
        const int c = i & (SLICE4_ - 1);
        xs4[i] = __ldg(x4 + b * (DM_ / 4) + cbase + c);
    }

    // warm L2 with the first two chunks of this warp's W rows while staging
    {
        const float* pf0 = W + (size_t)(row0 + (lane >> 3)) * DM_
                         + (size_t)cbase * 4 + (lane & 7) * 32;
        asm volatile("prefetch.global.L2 [%0];" :: "l"(pf0));
        asm volatile("prefetch.global.L2 [%0];" :: "l"(pf0 + 256));
    }
    __syncthreads();

    float acc[32];                            // acc[r*8+b]
    #pragma unroll
    for (int i = 0; i < 32; i++) acc[i] = 0.f;

    const float4* w0p = (const float4*)(W + (size_t)(row0 + 0) * DM_) + cbase;
    const float4* w1p = (const float4*)(W + (size_t)(row0 + 1) * DM_) + cbase;
    const float4* w2p = (const float4*)(W + (size_t)(row0 + 2) * DM_) + cbase;
    const float4* w3p = (const float4*)(W + (size_t)(row0 + 3) * DM_) + cbase;
    const float*  pfb = W + (size_t)(row0 + (lane >> 3)) * DM_
                      + (size_t)cbase * 4 + (lane & 7) * 32;

    #pragma unroll 2
    for (int it = 0; it < NIT_; ++it) {
        if (it + 2 < NIT_) {
            asm volatile("prefetch.global.L2 [%0];" :: "l"(pfb + (it + 2) * 256));
        }

        const int c0 = it * 64 + lane;        // local float4 col
        const int c1 = c0 + 32;
        const float4 wa0 = __ldcs(w0p + c0), wb0 = __ldcs(w0p + c1);
        const float4 wa1 = __ldcs(w1p + c0), wb1 = __ldcs(w1p + c1);
        const float4 wa2 = __ldcs(w2p + c0), wb2 = __ldcs(w2p + c1);
        const float4 wa3 = __ldcs(w3p + c0), wb3 = __ldcs(w3p + c1);
        #pragma unroll
        for (int b = 0; b < B_; b++) {
            const float4 xa = xs4[b * SLICE4_ + c0];
            acc[0 * 8 + b] += dot4(wa0, xa);
            acc[1 * 8 + b] += dot4(wa1, xa);
            acc[2 * 8 + b] += dot4(wa2, xa);
            acc[3 * 8 + b] += dot4(wa3, xa);
            const float4 xb = xs4[b * SLICE4_ + c1];
            acc[0 * 8 + b] += dot4(wb0, xb);
            acc[1 * 8 + b] += dot4(wb1, xb);
            acc[2 * 8 + b] += dot4(wb2, xb);
            acc[3 * 8 + b] += dot4(wb3, xb);
        }
    }

    // Butterfly transpose-reduce: lane L ends holding full sum of acc[L].
    #pragma unroll
    for (int o = 16; o >= 1; o >>= 1) {
        const bool up = (lane & o) != 0;
        #pragma unroll
        for (int k = 0; k < o; k++) {
            const float keep = up ? acc[k + o] : acc[k];
            const float send = up ? acc[k]     : acc[k + o];
            acc[k] = keep + __shfl_xor_sync(0xffffffffu, send, o);
        }
    }
    return acc[0];
}

__global__ void __launch_bounds__(256, 2)
proj_qkv_kernel(const float* __restrict__ q_in, const float* __restrict__ k_in,
                const float* __restrict__ v_in,
                const float* __restrict__ Wq, const float* __restrict__ Wk,
                const float* __restrict__ Wv) {
    extern __shared__ float4 xs4[];
    // clear combine flags/counters (stream-ordered before consumers; replay-safe)
    if (blockIdx.x == 0 && blockIdx.y == 0 && blockIdx.z == 0) {
        if (threadIdx.x < DM_ / 32)   g_flag[threadIdx.x] = 0;
        if (threadIdx.x < B_ * H_)    g_cnt[threadIdx.x] = 0;
    }
    const int ks = blockIdx.y;
    const float* x; const float* W; float* y;
    if (blockIdx.z == 0)      { x = q_in; W = Wq; y = g_qp[ks]; }
    else if (blockIdx.z == 1) { x = k_in; W = Wk; y = g_kp[ks]; }
    else                      { x = v_in; W = Wv; y = g_vp[ks]; }
    int row0;
    const float v = proj_core((const float4*)x, W, ks, xs4, &row0);
    const int lane = threadIdx.x & 31;
    y[(lane & 7) * DM_ + row0 + (lane >> 3)] = v;
}

// proj_out with in-kernel deterministic combine (R13 pattern, kept).
__global__ void __launch_bounds__(256, 2)
proj_out_kernel(const float* __restrict__ Wo, const float* __restrict__ bo,
                float* __restrict__ out) {
    extern __shared__ float4 xs4[];
    const int ks = blockIdx.y;
    int row0;
    const float v = proj_core((const float4*)g_attn, Wo, ks, xs4, &row0);
    const int lane = threadIdx.x & 31;
    const int b    = lane & 7;
    const int col  = row0 + (lane >> 3);
    const int idx  = b * DM_ + col;

    if (ks == 0) {
        g_op0[idx] = v;
        __threadfence();
        __syncthreads();
        if (threadIdx.x == 0) atomicExch(&g_flag[blockIdx.x], 1);
    } else {
        if (threadIdx.x == 0) {
            while (atomicAdd(&g_flag[blockIdx.x], 0) == 0) __nanosleep(64);
        }
        __syncthreads();
        __threadfence();
        const float p0 = __ldcg(&g_op0[idx]);
        out[idx] = (p0 + v) + __ldg(&bo[col]);
    }
}

// ---------------------------------------------------------------------------
// Attention, split-K over keys, with FUSED last-block reduce: each split
// block writes its partial, bumps a per-bh counter; the 4th arrival combines
// all 4 partials (fixed read order -> deterministic) and writes g_attn.
// ---------------------------------------------------------------------------
__global__ void __launch_bounds__(256)
attn_kernel(const float* __restrict__ kc, const float* __restrict__ vc,
            const float* __restrict__ bq, const float* __restrict__ bk,
            const float* __restrict__ bv, const int* __restrict__ cache_len_p) {
    const int bh = blockIdx.x;
    const int b  = bh >> 5;
    const int h  = bh & 31;
    const int s  = blockIdx.y;
    const int L  = cache_len_p[0] + 1;
    const int Lm1 = L - 1;
    const int chunk = (L + SPLIT_ - 1) / SPLIT_;
    const int start = s * chunk;
    const int end   = min(start + chunk, L);

    const int tid  = threadIdx.x;
    const int warp = tid >> 5;
    const int lane = tid & 31;

    const int voff = b * DM_ + h * DK_;
    const float scale = 0.08838834764831843f; // 1/sqrt(128)

    float4 q4   = ((const float4*)(bq + h * DK_))[lane];
    float4 Knew = ((const float4*)(bk + h * DK_))[lane];
    float4 Vnew = ((const float4*)(bv + h * DK_))[lane];
    #pragma unroll
    for (int ks = 0; ks < KSPLIT_; ks++) {
        q4   = add4(q4,   ((const float4*)(g_qp[ks] + voff))[lane]);
        Knew = add4(Knew, ((const float4*)(g_kp[ks] + voff))[lane]);
        Vnew = add4(Vnew, ((const float4*)(g_vp[ks] + voff))[lane]);
    }
    q4.x *= scale; q4.y *= scale; q4.z *= scale; q4.w *= scale;

    const float4* kb = (const float4*)(kc + (((size_t)b * H_ + h) * (size_t)MAXLEN_) * DK_);
    const float4* vb = (const float4*)(vc + (((size_t)b * H_ + h) * (size_t)MAXLEN_) * DK_);

    float m = -CUDART_INF_F;
    float lsum = 0.f;
    float4 a = make_float4(0.f, 0.f, 0.f, 0.f);

    int key = start + warp;
    for (; key + 24 < end; key += 32) {
        const int k1 = key, k2 = key + 8, k3 = key + 16, k4 = key + 24;
        float4 K1 = __ldcs(kb + (size_t)k1 * 32 + lane);
        float4 K2 = __ldcs(kb + (size_t)k2 * 32 + lane);
        float4 K3 = __ldcs(kb + (size_t)k3 * 32 + lane);
        float4 K4 = __ldcs(kb + (size_t)k4 * 32 + lane);
        float4 V1 = __ldcs(vb + (size_t)k1 * 32 + lane);
        float4 V2 = __ldcs(vb + (size_t)k2 * 32 + lane);
        float4 V3 = __ldcs(vb + (size_t)k3 * 32 + lane);
        float4 V4 = __ldcs(vb + (size_t)k4 * 32 + lane);
        if (k1 == Lm1) { K1 = Knew; V1 = Vnew; }
        if (k2 == Lm1) { K2 = Knew; V2 = Vnew; }
        if (k3 == Lm1) { K3 = Knew; V3 = Vnew; }
        if (k4 == Lm1) { K4 = Knew; V4 = Vnew; }

        float s1 = dot4(q4, K1);
        float s2 = dot4(q4, K2);
        float s3 = dot4(q4, K3);
        float s4 = dot4(q4, K4);
        #pragma unroll
        for (int o = 16; o > 0; o >>= 1) {
            s1 += __shfl_xor_sync(0xffffffffu, s1, o);
            s2 += __shfl_xor_sync(0xffffffffu, s2, o);
            s3 += __shfl_xor_sync(0xffffffffu, s3, o);
            s4 += __shfl_xor_sync(0xffffffffu, s4, o);
        }

        const float mn = fmaxf(fmaxf(m, fmaxf(s1, s2)), fmaxf(s3, s4));
        const float corr = __expf(m - mn);
        const float p1 = __expf(s1 - mn);
        const float p2 = __expf(s2 - mn);
        const float p3 = __expf(s3 - mn);
        const float p4 = __expf(s4 - mn);
        lsum = lsum * corr + (p1 + p2) + (p3 + p4);
        a.x = a.x * corr + p1 * V1.x + p2 * V2.x + p3 * V3.x + p4 * V4.x;
        a.y = a.y * corr + p1 * V1.y + p2 * V2.y + p3 * V3.y + p4 * V4.y;
        a.z = a.z * corr + p1 * V1.z + p2 * V2.z + p3 * V3.z + p4 * V4.z;
        a.w = a.w * corr + p1 * V1.w + p2 * V2.w + p3 * V3.w + p4 * V4.w;
        m = mn;
    }
    for (; key < end; key += 8) {
        float4 K1 = __ldcs(kb + (size_t)key * 32 + lane);
        float4 V1 = __ldcs(vb + (size_t)key * 32 + lane);
        if (key == Lm1) { K1 = Knew; V1 = Vnew; }
        float s1 = dot4(q4, K1);
        #pragma unroll
        for (int o = 16; o > 0; o >>= 1) s1 += __shfl_xor_sync(0xffffffffu, s1, o);
        const float mn = fmaxf(m, s1);
        const float corr = __expf(m - mn);
        const float p1 = __expf(s1 - mn);
        lsum = lsum * corr + p1;
        a.x = a.x * corr + p1 * V1.x;
        a.y = a.y * corr + p1 * V1.y;
        a.z = a.z * corr + p1 * V1.z;
        a.w = a.w * corr + p1 * V1.w;
        m = mn;
    }

    // cross-warp combine -> unnormalized block partial
    __shared__ float  sm_m[8];
    __shared__ float  sm_l[8];
    __shared__ float4 sm_a[8][32];
    __shared__ int    sm_last;
    if (lane == 0) { sm_m[warp] = m; sm_l[warp] = lsum; }
    sm_a[warp][lane] = a;
    __syncthreads();

    if (tid < 128) {
        float M = sm_m[0];
        #pragma unroll
        for (int w = 1; w < 8; w++) M = fmaxf(M, sm_m[w]);
        float Ls = 0.f, o = 0.f;
        const float* sa = (const float*)sm_a;  // [8][128]
        #pragma unroll
        for (int w = 0; w < 8; w++) {
            const float e = __expf(sm_m[w] - M);
            Ls += e * sm_l[w];
            o  += e * sa[w * 128 + tid];
        }
        const int idx = bh * SPLIT_ + s;
        g_pa[idx * DK_ + tid] = o;
        if (tid == 0) { g_pm[idx] = M; g_pl[idx] = Ls; }
    }

    // last split block for this bh performs the combine
    __threadfence();
    __syncthreads();
    if (tid == 0) sm_last = (atomicAdd(&g_cnt[bh], 1) == SPLIT_ - 1) ? 1 : 0;
    __syncthreads();
    if (sm_last && tid < DK_) {
        float pm[SPLIT_], pl[SPLIT_];
        float M = -CUDART_INF_F;
        #pragma unroll
        for (int ss = 0; ss < SPLIT_; ss++) {
            pm[ss] = __ldcg(&g_pm[bh * SPLIT_ + ss]);
            pl[ss] = __ldcg(&g_pl[bh * SPLIT_ + ss]);
            M = fmaxf(M, pm[ss]);
        }
        float Ls = 0.f, o = 0.f;
        #pragma unroll
        for (int ss = 0; ss < SPLIT_; ss++) {
            const float e = __expf(pm[ss] - M);
            Ls += e * pl[ss];
            o  += e * __ldcg(&g_pa[(bh * SPLIT_ + ss) * DK_ + tid]);
        }
        g_attn[bh * DK_ + tid] = o / Ls;
    }
}

// ---------------------------------------------------------------------------
extern "C" void kernel_launch(void* const* d_in, const int* in_sizes, int n_in,
                              void* d_out, int out_size) {
    const float* query = (const float*)d_in[0];
    const float* keyv  = (const float*)d_in[1];
    const float* value = (const float*)d_in[2];
    const float* kc    = (const float*)d_in[3];
    const float* vc    = (const float*)d_in[4];
    const float* Wq    = (const float*)d_in[5];
    const float* bq    = (const float*)d_in[6];
    const float* Wk    = (const float*)d_in[7];
    const float* bk    = (const float*)d_in[8];
    const float* Wv    = (const float*)d_in[9];
    const float* bv    = (const float*)d_in[10];
    const float* Wo    = (const float*)d_in[11];
    const float* bo    = (const float*)d_in[12];
    const int*   clp   = (const int*)d_in[13];

    const int smem = B_ * SLICE4_ * sizeof(float4);   // 64 KB
    cudaFuncSetAttribute(proj_qkv_kernel, cudaFuncAttributeMaxDynamicSharedMemorySize, smem);
    cudaFuncSetAttribute(proj_out_kernel, cudaFuncAttributeMaxDynamicSharedMemorySize, smem);

    dim3 gqkv(DM_ / 32, KSPLIT_, 3);
    proj_qkv_kernel<<<gqkv, 256, smem>>>(query, keyv, value, Wq, Wk, Wv);
    dim3 gattn(B_ * H_, SPLIT_);
    attn_kernel<<<gattn, 256>>>(kc, vc, bq, bk, bv, clp);
    dim3 gout(DM_ / 32, KSPLIT_);
    proj_out_kernel<<<gout, 256, smem>>>(Wo, bo, (float*)d_out);
}